// round 1
// baseline (speedup 1.0000x reference)
#include <cuda_runtime.h>
#include <cuda_bf16.h>

// Masked mean: mean of (x - y) where x > y, over 32*1024*1024 fp32 elements.
// HBM-bound streaming reduction. float4 vectorized grid-stride + block reduce
// + atomic partials into __device__ globals (no allocations).

__device__ float               g_sum;
__device__ unsigned long long  g_cnt;

__global__ void init_kernel() {
    g_sum = 0.0f;
    g_cnt = 0ull;
}

__global__ __launch_bounds__(256) void reduce_kernel(
    const float4* __restrict__ x4,
    const float4* __restrict__ y4,
    int n4)
{
    float fsum = 0.0f;
    unsigned int cnt = 0;

    int stride = gridDim.x * blockDim.x;
    for (int i = blockIdx.x * blockDim.x + threadIdx.x; i < n4; i += stride) {
        float4 xv = __ldg(&x4[i]);
        float4 yv = __ldg(&y4[i]);

        float d0 = xv.x - yv.x;
        float d1 = xv.y - yv.y;
        float d2 = xv.z - yv.z;
        float d3 = xv.w - yv.w;

        if (d0 > 0.0f) { fsum += d0; cnt++; }
        if (d1 > 0.0f) { fsum += d1; cnt++; }
        if (d2 > 0.0f) { fsum += d2; cnt++; }
        if (d3 > 0.0f) { fsum += d3; cnt++; }
    }

    // warp reduce
    #pragma unroll
    for (int off = 16; off > 0; off >>= 1) {
        fsum += __shfl_down_sync(0xFFFFFFFFu, fsum, off);
        cnt  += __shfl_down_sync(0xFFFFFFFFu, cnt,  off);
    }

    __shared__ float        s_sum[8];
    __shared__ unsigned int s_cnt[8];
    int lane = threadIdx.x & 31;
    int wid  = threadIdx.x >> 5;
    if (lane == 0) { s_sum[wid] = fsum; s_cnt[wid] = cnt; }
    __syncthreads();

    if (wid == 0) {
        fsum = (lane < 8) ? s_sum[lane] : 0.0f;
        cnt  = (lane < 8) ? s_cnt[lane] : 0u;
        #pragma unroll
        for (int off = 4; off > 0; off >>= 1) {
            fsum += __shfl_down_sync(0xFFFFFFFFu, fsum, off);
            cnt  += __shfl_down_sync(0xFFFFFFFFu, cnt,  off);
        }
        if (lane == 0) {
            atomicAdd(&g_sum, fsum);
            atomicAdd(&g_cnt, (unsigned long long)cnt);
        }
    }
}

__global__ void finalize_kernel(float* __restrict__ out) {
    unsigned long long c = g_cnt;
    out[0] = (c > 0ull) ? (g_sum / (float)c) : 0.0f;
}

extern "C" void kernel_launch(void* const* d_in, const int* in_sizes, int n_in,
                              void* d_out, int out_size) {
    const float* x = (const float*)d_in[0];
    const float* y = (const float*)d_in[1];
    float* out = (float*)d_out;

    int n  = in_sizes[0];      // 33554432, divisible by 4
    int n4 = n >> 2;

    init_kernel<<<1, 1>>>();

    const int threads = 256;
    const int blocks  = 148 * 8;   // 1184 blocks, ~28 float4 iters/thread
    reduce_kernel<<<blocks, threads>>>(
        (const float4*)x, (const float4*)y, n4);

    finalize_kernel<<<1, 1>>>(out);
}

// round 2
// speedup vs baseline: 1.0063x; 1.0063x over previous
#include <cuda_runtime.h>
#include <cuda_bf16.h>

// Masked mean: mean of (x - y) where x > y, over 32M fp32 elements.
// Single fused kernel: grid-stride float4 reduction + last-block-done
// finalize. __device__ globals self-reset each call -> graph-replay safe,
// no init/finalize launches (saves ~6us of launch serialization).

__device__ float               g_sum;     // zero-initialized at load
__device__ unsigned long long  g_cnt;
__device__ unsigned int        g_ticket;

__global__ __launch_bounds__(256) void fused_reduce_kernel(
    const float4* __restrict__ x4,
    const float4* __restrict__ y4,
    int n4,
    float* __restrict__ out)
{
    float fsum = 0.0f;
    unsigned int cnt = 0;

    int stride = gridDim.x * blockDim.x;
    for (int i = blockIdx.x * blockDim.x + threadIdx.x; i < n4; i += stride) {
        float4 xv = __ldg(&x4[i]);
        float4 yv = __ldg(&y4[i]);

        float d0 = xv.x - yv.x;
        float d1 = xv.y - yv.y;
        float d2 = xv.z - yv.z;
        float d3 = xv.w - yv.w;

        // branchless: positive part + predicate count
        fsum += fmaxf(d0, 0.0f);
        fsum += fmaxf(d1, 0.0f);
        fsum += fmaxf(d2, 0.0f);
        fsum += fmaxf(d3, 0.0f);
        cnt  += (d0 > 0.0f) + (d1 > 0.0f) + (d2 > 0.0f) + (d3 > 0.0f);
    }

    // warp reduce
    #pragma unroll
    for (int off = 16; off > 0; off >>= 1) {
        fsum += __shfl_down_sync(0xFFFFFFFFu, fsum, off);
        cnt  += __shfl_down_sync(0xFFFFFFFFu, cnt,  off);
    }

    __shared__ float        s_sum[8];
    __shared__ unsigned int s_cnt[8];
    __shared__ bool         s_last;
    int lane = threadIdx.x & 31;
    int wid  = threadIdx.x >> 5;
    if (lane == 0) { s_sum[wid] = fsum; s_cnt[wid] = cnt; }
    __syncthreads();

    if (wid == 0) {
        fsum = (lane < 8) ? s_sum[lane] : 0.0f;
        cnt  = (lane < 8) ? s_cnt[lane] : 0u;
        #pragma unroll
        for (int off = 4; off > 0; off >>= 1) {
            fsum += __shfl_down_sync(0xFFFFFFFFu, fsum, off);
            cnt  += __shfl_down_sync(0xFFFFFFFFu, cnt,  off);
        }
        if (lane == 0) {
            atomicAdd(&g_sum, fsum);
            atomicAdd(&g_cnt, (unsigned long long)cnt);
            __threadfence();
            unsigned int t = atomicAdd(&g_ticket, 1u);
            s_last = (t == gridDim.x - 1);
        }
    }
    __syncthreads();

    // Last block finishes: write result, reset globals for next replay.
    if (s_last && threadIdx.x == 0) {
        __threadfence();  // ensure all blocks' atomics are visible
        float              fs = g_sum;
        unsigned long long c  = g_cnt;
        out[0] = (c > 0ull) ? (fs / (float)c) : 0.0f;
        // reset for next graph replay (deterministic across calls)
        g_sum    = 0.0f;
        g_cnt    = 0ull;
        g_ticket = 0u;
        __threadfence();
    }
}

extern "C" void kernel_launch(void* const* d_in, const int* in_sizes, int n_in,
                              void* d_out, int out_size) {
    const float* x = (const float*)d_in[0];
    const float* y = (const float*)d_in[1];
    float* out = (float*)d_out;

    int n  = in_sizes[0];      // 33554432, divisible by 4
    int n4 = n >> 2;

    const int threads = 256;
    const int blocks  = 148 * 8;   // full occupancy: 8 CTAs/SM x 256 thr
    fused_reduce_kernel<<<blocks, threads>>>(
        (const float4*)x, (const float4*)y, n4, out);
}